// round 3
// baseline (speedup 1.0000x reference)
#include <cuda_runtime.h>
#include <cstdint>

// LightGCN: out = 0.25*(X + h1 + h2 + h3), h_{k+1} = A h_k (weighted scatter-sum)
// Pull-based: build dst-sorted CSR per launch, then 3 atomic-free gather layers.

#define N_NODES 100000
#define D_FEAT  64
#define MAX_E   1600000
#define SCAN_BS 1024
#define N_SCAN_BLOCKS ((N_NODES + SCAN_BS - 1) / SCAN_BS)   // 98

// Static scratch (no allocation allowed).
__device__ float g_bufA[(size_t)N_NODES * D_FEAT];
__device__ float g_bufB[(size_t)N_NODES * D_FEAT];
__device__ int   g_deg[N_NODES];
__device__ int   g_incl[N_NODES];
__device__ int   g_blockSums[N_SCAN_BLOCKS];
__device__ int   g_blockOff[N_SCAN_BLOCKS];
__device__ int   g_off[N_NODES + 1];
__device__ int   g_cursor[N_NODES];
__device__ int2  g_sedge[MAX_E];     // packed (src, ew-as-int), dst-sorted

// ---------------- CSR construction ----------------

__global__ void k_zero_deg(int n4) {
    int i = blockIdx.x * blockDim.x + threadIdx.x;
    if (i < n4) reinterpret_cast<int4*>(g_deg)[i] = make_int4(0, 0, 0, 0);
}

__global__ void k_hist(const int* __restrict__ dst, int nE) {
    int e = blockIdx.x * blockDim.x + threadIdx.x;
    if (e < nE) atomicAdd(&g_deg[dst[e]], 1);
}

// Per-block inclusive scan (Hillis-Steele) + block sums.
__global__ void k_scan_block(int n) {
    __shared__ int sh[SCAN_BS];
    int t = threadIdx.x;
    int i = blockIdx.x * SCAN_BS + t;
    int v = (i < n) ? g_deg[i] : 0;
    sh[t] = v;
    __syncthreads();
    for (int d = 1; d < SCAN_BS; d <<= 1) {
        int x = (t >= d) ? sh[t - d] : 0;
        __syncthreads();
        sh[t] += x;
        __syncthreads();
    }
    if (i < n) g_incl[i] = sh[t];
    if (t == SCAN_BS - 1) g_blockSums[blockIdx.x] = sh[t];
}

// Parallel exclusive scan of the 98 block sums (single 128-thread block).
__global__ void k_scan_tops() {
    __shared__ int sh[128];
    int t = threadIdx.x;
    int v = (t < N_SCAN_BLOCKS) ? g_blockSums[t] : 0;
    sh[t] = v;
    __syncthreads();
    for (int d = 1; d < 128; d <<= 1) {
        int x = (t >= d) ? sh[t - d] : 0;
        __syncthreads();
        sh[t] += x;
        __syncthreads();
    }
    if (t < N_SCAN_BLOCKS) g_blockOff[t] = sh[t] - v;   // exclusive
}

__global__ void k_finalize_off(int n, int nE) {
    int i = blockIdx.x * blockDim.x + threadIdx.x;
    if (i >= n) return;
    int excl = g_incl[i] + g_blockOff[i >> 10] - g_deg[i];
    g_off[i] = excl;
    g_cursor[i] = excl;
    if (i == n - 1) g_off[n] = nE;
}

__global__ void k_scatter(const int* __restrict__ src,
                          const int* __restrict__ dst,
                          const float* __restrict__ ew, int nE) {
    int e = blockIdx.x * blockDim.x + threadIdx.x;
    if (e >= nE) return;
    int d = dst[e];
    int pos = atomicAdd(&g_cursor[d], 1);
    g_sedge[pos] = make_int2(src[e], __float_as_int(ew[e]));
}

// ---------------- Pull SpMM ----------------
// One warp per dst node. Lanes 0-15 = even edges, 16-31 = odd edges; each lane
// owns one float4 column chunk. Inner loop unrolled 2x -> 2 independent
// gathers in flight per lane (4 per node) to cover the ~234cyc L2 latency.

__device__ __forceinline__ float4 warp_node_reduce(const float* __restrict__ Xin,
                                                   int node, int c, int half) {
    int begin = g_off[node], end = g_off[node + 1];
    float4 acc0 = make_float4(0.f, 0.f, 0.f, 0.f);
    float4 acc1 = make_float4(0.f, 0.f, 0.f, 0.f);
    int e = begin + half;
    for (; e + 2 < end; e += 4) {
        int2 p0 = g_sedge[e];
        int2 p1 = g_sedge[e + 2];
        float4 v0 = *reinterpret_cast<const float4*>(Xin + (size_t)p0.x * D_FEAT + (c << 2));
        float4 v1 = *reinterpret_cast<const float4*>(Xin + (size_t)p1.x * D_FEAT + (c << 2));
        float w0 = __int_as_float(p0.y);
        float w1 = __int_as_float(p1.y);
        acc0.x += w0 * v0.x; acc0.y += w0 * v0.y; acc0.z += w0 * v0.z; acc0.w += w0 * v0.w;
        acc1.x += w1 * v1.x; acc1.y += w1 * v1.y; acc1.z += w1 * v1.z; acc1.w += w1 * v1.w;
    }
    if (e < end) {
        int2 p0 = g_sedge[e];
        float4 v0 = *reinterpret_cast<const float4*>(Xin + (size_t)p0.x * D_FEAT + (c << 2));
        float w0 = __int_as_float(p0.y);
        acc0.x += w0 * v0.x; acc0.y += w0 * v0.y; acc0.z += w0 * v0.z; acc0.w += w0 * v0.w;
    }
    acc0.x += acc1.x; acc0.y += acc1.y; acc0.z += acc1.z; acc0.w += acc1.w;
    // combine the two edge-halves (same columns in both halves)
    acc0.x += __shfl_xor_sync(0xffffffff, acc0.x, 16);
    acc0.y += __shfl_xor_sync(0xffffffff, acc0.y, 16);
    acc0.z += __shfl_xor_sync(0xffffffff, acc0.z, 16);
    acc0.w += __shfl_xor_sync(0xffffffff, acc0.w, 16);
    return acc0;
}

__global__ void k_pull(const float* __restrict__ Xin,
                       float* __restrict__ Xout) {
    int gwarp = (blockIdx.x * blockDim.x + threadIdx.x) >> 5;
    if (gwarp >= N_NODES) return;
    int lane = threadIdx.x & 31;
    int half = lane >> 4;
    int c    = lane & 15;
    float4 acc = warp_node_reduce(Xin, gwarp, c, half);
    if (half == 0)
        *reinterpret_cast<float4*>(Xout + (size_t)gwarp * D_FEAT + (c << 2)) = acc;
}

// Final layer fused with the mean: out = 0.25*(X + h1 + h2 + h3)
__global__ void k_pull_final(const float* __restrict__ Xin,   // h2
                             const float* __restrict__ X,
                             const float* __restrict__ h1,
                             float* __restrict__ out) {
    int gwarp = (blockIdx.x * blockDim.x + threadIdx.x) >> 5;
    if (gwarp >= N_NODES) return;
    int lane = threadIdx.x & 31;
    int half = lane >> 4;
    int c    = lane & 15;
    float4 acc = warp_node_reduce(Xin, gwarp, c, half);   // h3 chunk
    if (half == 0) {
        size_t idx = (size_t)gwarp * D_FEAT + (c << 2);
        float4 x0 = *reinterpret_cast<const float4*>(X   + idx);
        float4 x1 = *reinterpret_cast<const float4*>(h1  + idx);
        float4 x2 = *reinterpret_cast<const float4*>(Xin + idx);
        float4 o;
        o.x = 0.25f * (x0.x + x1.x + x2.x + acc.x);
        o.y = 0.25f * (x0.y + x1.y + x2.y + acc.y);
        o.z = 0.25f * (x0.z + x1.z + x2.z + acc.z);
        o.w = 0.25f * (x0.w + x1.w + x2.w + acc.w);
        *reinterpret_cast<float4*>(out + idx) = o;
    }
}

extern "C" void kernel_launch(void* const* d_in, const int* in_sizes, int n_in,
                              void* d_out, int out_size) {
    const float* X   = (const float*)d_in[0];
    const int*   src = (const int*)  d_in[1];
    const int*   dst = (const int*)  d_in[2];
    const float* ew  = (const float*)d_in[3];
    float* out = (float*)d_out;

    const int nE = in_sizes[1];

    float* bufA = nullptr;
    float* bufB = nullptr;
    cudaGetSymbolAddress((void**)&bufA, g_bufA);
    cudaGetSymbolAddress((void**)&bufB, g_bufB);

    const int TB = 256;
    const int gridNode = (N_NODES + TB - 1) / TB;
    const int gridZ    = (N_NODES / 4 + TB - 1) / TB;
    const int gridE    = (nE + TB - 1) / TB;
    const int gridPull = (N_NODES * 32 + TB - 1) / TB;   // warp per node

    // --- build dst-sorted CSR ---
    k_zero_deg<<<gridZ, TB>>>(N_NODES / 4);
    k_hist<<<gridE, TB>>>(dst, nE);
    k_scan_block<<<N_SCAN_BLOCKS, SCAN_BS>>>(N_NODES);
    k_scan_tops<<<1, 128>>>();
    k_finalize_off<<<gridNode, TB>>>(N_NODES, nE);
    k_scatter<<<gridE, TB>>>(src, dst, ew, nE);

    // --- 3 pull layers, final fused with the mean ---
    k_pull<<<gridPull, TB>>>(X, bufA);                    // h1
    k_pull<<<gridPull, TB>>>(bufA, bufB);                 // h2
    k_pull_final<<<gridPull, TB>>>(bufB, X, bufA, out);   // h3 + mean
}